// round 10
// baseline (speedup 1.0000x reference)
#include <cuda_runtime.h>
#include <math.h>

typedef unsigned long long ull;

#define THREADS 1024
#define NSTATE  16384

// aux float offsets (aux = sm + 2*NSTATE floats)
#define OF_GATE 0      // 42 gates * 8 floats: [ca,ca,-sa,-sa,sa,sa,cf,sf]
#define OF_PHI  336    // 42 (phi = 0.5*theta for RZ), padded
#define OF_ENC_C 384   // 14
#define OF_ENC_S 400   // 14
#define OF_RTAB 416    // 16
#define OF_PR   432    // 2 layers * 16 * 4 (wires 8-11, keyed by pass-C r)
#define OF_TL   560    // 2 layers * 32 * 2 (wires 13,12,7,6,5, keyed by pass-C lane)
#define OF_TH   688    // 2 layers * 32 * 2 (wires 4,3,2,1,0, keyed by pass-C wa)
#define OF_TLO  816    // 128
#define OF_THI  944    // 128
#define OF_WARP 1072   // 32
#define AUXF    1104
#define SMEM_BYTES ((2 * NSTATE + AUXF) * sizeof(float))

// Named partial barriers. NEVER id 0 (owned by __syncthreads).
#define BAR_SYNC(id, cnt) \
    asm volatile("bar.sync %0, %1;" :: "r"(id), "r"(cnt) : "memory")

__device__ __forceinline__ ull pk(float lo, float hi) {
    ull r; asm("mov.b64 %0, {%1,%2};" : "=l"(r) : "f"(lo), "f"(hi)); return r;
}
__device__ __forceinline__ void upk(ull v, float& lo, float& hi) {
    asm("mov.b64 {%0,%1}, %2;" : "=f"(lo), "=f"(hi) : "l"(v));
}
__device__ __forceinline__ ull swap2(ull v) {
    float lo, hi;
    asm("mov.b64 {%0,%1}, %2;" : "=f"(lo), "=f"(hi) : "l"(v));
    ull r; asm("mov.b64 %0, {%1,%2};" : "=l"(r) : "f"(hi), "f"(lo)); return r;
}
__device__ __forceinline__ ull mul2(ull a, ull b) {
    ull d; asm("mul.rn.f32x2 %0, %1, %2;" : "=l"(d) : "l"(a), "l"(b)); return d;
}
__device__ __forceinline__ ull fma2(ull a, ull b, ull c) {
    ull d; asm("fma.rn.f32x2 %0, %1, %2, %3;" : "=l"(d) : "l"(a), "l"(b), "l"(c)); return d;
}
// A * e^{i a}: cr2 = (c,c), cn2 = (-s,s)
__device__ __forceinline__ ull phmul(ull A, ull cr2, ull cn2) {
    return fma2(cn2, swap2(A), mul2(cr2, A));
}
__device__ __forceinline__ void pair_ry(ull& A0, ull& A1,
                                        ull ca2, ull nsa2, ull sa2) {
    ull T0 = fma2(nsa2, A1, mul2(ca2, A0));
    ull T1 = fma2(sa2,  A0, mul2(ca2, A1));
    A0 = T0; A1 = T1;
}
__device__ __forceinline__ void shfl_ry(ull& A, unsigned mask, ull ca2, ull sp) {
    ull P = __shfl_xor_sync(0xffffffffu, A, mask);
    A = fma2(sp, P, mul2(ca2, A));
}

__global__ __launch_bounds__(THREADS, 1)
void qsim_kernel(const float* __restrict__ state,   // [256,14]
                 const float* __restrict__ vp,      // [3,14,3]
                 const float* __restrict__ hw,      // [14]
                 const float* __restrict__ hb,      // [1]
                 float* __restrict__ out)           // [256]
{
    extern __shared__ float sm[];
    ull*   psi = (ull*)sm;                 // 16384 packed (re,im), address = h(e)
    float* aux = sm + 2 * NSTATE;

    const int tid  = threadIdx.x;
    const int lane = tid & 31;
    const int wa   = tid >> 5;

    // ---- setup stage 1 ----
    if (tid < 42) {
        float a  = 0.5f * vp[tid * 3 + 0];
        float th = 0.5f * vp[tid * 3 + 1];
        float ca, sa, cf, sf;
        sincosf(a,  &sa, &ca);
        sincosf(th, &sf, &cf);
        float* g = aux + OF_GATE + tid * 8;
        g[0] = ca;  g[1] = ca;
        g[2] = -sa; g[3] = -sa;
        g[4] = sa;  g[5] = sa;
        g[6] = cf;  g[7] = sf;
        aux[OF_PHI + tid] = th;
    } else if (tid >= 64 && tid < 78) {
        int w = tid - 64;
        float h = 0.5f * state[blockIdx.x * 14 + w];
        float c, s;
        sincosf(h, &s, &c);
        aux[OF_ENC_C + w] = c;
        aux[OF_ENC_S + w] = s;
    } else if (tid >= 128 && tid < 256) {
        int x = tid - 128;
        float a2 = 0.f;
        #pragma unroll
        for (int p = 0; p < 7; p++)
            a2 += (((x >> p) & 1) ? -1.f : 1.f) * hw[13 - p];
        aux[OF_TLO + x] = a2;
    } else if (tid >= 256 && tid < 384) {
        int x = tid - 256;
        float a2 = 0.f;
        #pragma unroll
        for (int p = 0; p < 7; p++)
            a2 += (((x >> p) & 1) ? -1.f : 1.f) * hw[6 - p];
        aux[OF_THI + x] = a2;
    }
    __syncthreads();

    // ---- setup stage 2 ----
    if (tid < 16) {
        float m = 1.f;
        #pragma unroll
        for (int j = 0; j < 4; j++)
            m *= ((tid >> j) & 1) ? aux[OF_ENC_S + 3 - j] : aux[OF_ENC_C + 3 - j];
        aux[OF_RTAB + tid] = m;
    } else if (tid >= 32 && tid < 64) {
        // PR: wires 8-11 phase, keyed by pass-C r
        int idx = tid - 32;
        int l = idx >> 4, r = idx & 15;
        const float* ph = aux + OF_PHI + l * 14;
        float ang = (( r       & 1) ? ph[11] : -ph[11])
                  + (((r >> 1) & 1) ? ph[10] : -ph[10])
                  + (((r >> 2) & 1) ? ph[9]  : -ph[9])
                  + (((r >> 3) & 1) ? ph[8]  : -ph[8]);
        float c, s;
        sincosf(ang, &s, &c);
        float* p = aux + OF_PR + (l * 16 + r) * 4;
        p[0] = c; p[1] = c; p[2] = -s; p[3] = s;
    } else if (tid >= 64 && tid < 128) {
        // TL: pass-C lane bits -> wires 13,12,7,6,5
        int idx = tid - 64;
        int l = idx >> 5, ln = idx & 31;
        const float* ph = aux + OF_PHI + l * 14;
        float ang = (( ln       & 1) ? ph[13] : -ph[13])
                  + (((ln >> 1) & 1) ? ph[12] : -ph[12])
                  + (((ln >> 2) & 1) ? ph[7]  : -ph[7])
                  + (((ln >> 3) & 1) ? ph[6]  : -ph[6])
                  + (((ln >> 4) & 1) ? ph[5]  : -ph[5]);
        float c, s;
        sincosf(ang, &s, &c);
        aux[OF_TL + (l * 32 + ln) * 2]     = c;
        aux[OF_TL + (l * 32 + ln) * 2 + 1] = s;
    } else if (tid >= 128 && tid < 192) {
        // TH: pass-C wa bits -> wires 4,3,2,1,0
        int idx = tid - 128;
        int l = idx >> 5, w5 = idx & 31;
        const float* ph = aux + OF_PHI + l * 14;
        float ang = (( w5       & 1) ? ph[4] : -ph[4])
                  + (((w5 >> 1) & 1) ? ph[3] : -ph[3])
                  + (((w5 >> 2) & 1) ? ph[2] : -ph[2])
                  + (((w5 >> 3) & 1) ? ph[1] : -ph[1])
                  + (((w5 >> 4) & 1) ? ph[0] : -ph[0]);
        float c, s;
        sincosf(ang, &s, &c);
        aux[OF_TH + (l * 32 + w5) * 2]     = c;
        aux[OF_TH + (l * 32 + w5) * 2 + 1] = s;
    }
    // per-thread RX base product over tid bits 0..9 (wires 13..4)
    float P = 1.f;
    #pragma unroll
    for (int j = 0; j < 10; j++)
        P *= ((tid >> j) & 1) ? aux[OF_ENC_S + 13 - j] : aux[OF_ENC_C + 13 - j];
    int pt = __popc(tid);
    __syncthreads();

    // ---- init directly in pass-A register layout: e = tid | (r<<10) ----
    ull A[16];
    #pragma unroll
    for (int r = 0; r < 16; r++) {
        float mag = P * aux[OF_RTAB + r];
        int k = (pt + __popc(r)) & 3;
        float sg = (k == 1 || k == 2) ? -mag : mag;
        float re_ = (k & 1) ? 0.f : sg;
        float im_ = (k & 1) ? sg : 0.f;
        A[r] = pk(re_, im_);
    }

    float acc = 0.f;

    // ---- address bases under global map h(e) = e ^ (((e>>6)&7)<<2) ----
    const int baseA_st = tid ^ (((tid >> 6) & 7) << 2);
    const int gt = tid ^ (tid >> 1);
    const int baseA_ld = gt ^ (((gt >> 6) & 7) << 2);
    const int base_B = lane | ((wa & 1) << 5) | ((wa >> 1) << 10);
    const int eC_hi = (((lane >> 2) & 7) << 6) | (wa << 9);
    const int base_C = ((lane & 3) | eC_hi) ^ (((lane >> 2) & 7) << 2);
    const int e_baseC = (lane & 3) | eC_hi;

    // group-barrier ids (never 0): A->B parity = 5+(wa&1) cnt 512;
    // B->C octet = 1+(wa>>3) cnt 256 (superset of the {2k,2k+1} writer pair)
    const int barAB = 5 + (wa & 1);
    const int barBC = 1 + (wa >> 3);

    #pragma unroll
    for (int l = 0; l < 3; l++) {
        // ======== Pass A: wires 0-3 pair (r bits), wires 12,13 shfl ========
        if (l) {
            #pragma unroll
            for (int r = 0; r < 16; r++)
                A[r] = psi[baseA_ld ^ (((r ^ (r << 1)) & 31) << 9)];
            __syncthreads();   // gather set != scatter set
        }
        #pragma unroll
        for (int w = 12; w < 14; w++) {
            const ull* g = (const ull*)(aux + OF_GATE + (l * 14 + w) * 8);
            int bit = 13 - w;
            ull ca2 = g[0];
            ull sp  = ((lane >> bit) & 1) ? g[2] : g[1];
            unsigned mask = 1u << bit;
            #pragma unroll
            for (int r = 0; r < 16; r++)
                shfl_ry(A[r], mask, ca2, sp);
        }
        #pragma unroll
        for (int w = 0; w < 4; w++) {
            const ull* g = (const ull*)(aux + OF_GATE + (l * 14 + w) * 8);
            ull ca2 = g[0], nsa2 = g[1], sa2 = g[2];
            int bj = 1 << (3 - w);
            #pragma unroll
            for (int r = 0; r < 16; r++)
                if (!(r & bj))
                    pair_ry(A[r], A[r | bj], ca2, nsa2, sa2);
        }
        #pragma unroll
        for (int r = 0; r < 16; r++)
            psi[baseA_st | (r << 10)] = A[r];
        BAR_SYNC(barAB, 512);   // B reads only same-parity A-writers

        // ======== Pass B: wires 4-7 pair ========
        #pragma unroll
        for (int r = 0; r < 16; r++)
            A[r] = psi[base_B ^ ((r << 6) | ((r & 7) << 2))];
        #pragma unroll
        for (int w = 4; w < 8; w++) {
            const ull* g = (const ull*)(aux + OF_GATE + (l * 14 + w) * 8);
            ull ca2 = g[0], nsa2 = g[1], sa2 = g[2];
            int bj = 1 << (7 - w);
            #pragma unroll
            for (int r = 0; r < 16; r++)
                if (!(r & bj))
                    pair_ry(A[r], A[r | bj], ca2, nsa2, sa2);
        }
        #pragma unroll
        for (int r = 0; r < 16; r++)
            psi[base_B ^ ((r << 6) | ((r & 7) << 2))] = A[r];
        BAR_SYNC(barBC, 256);   // C reads only from its B warp-pair (in-octet)

        // ======== Pass C: wires 8-11 pair ========
        #pragma unroll
        for (int r = 0; r < 16; r++)
            A[r] = psi[base_C ^ (r << 2)];
        #pragma unroll
        for (int w = 8; w < 12; w++) {
            const ull* g = (const ull*)(aux + OF_GATE + (l * 14 + w) * 8);
            ull ca2 = g[0], nsa2 = g[1], sa2 = g[2];
            int bj = 1 << (11 - w);
            #pragma unroll
            for (int r = 0; r < 16; r++)
                if (!(r & bj))
                    pair_ry(A[r], A[r | bj], ca2, nsa2, sa2);
        }

        if (l < 2) {
            // ---- all 14 wires' RZ phases once: TL[lane]*TH[wa]*PR[r] ----
            const float* tl = aux + OF_TL + (l * 32 + lane) * 2;
            const float* th = aux + OF_TH + (l * 32 + wa) * 2;
            float c1 = tl[0], s1 = tl[1], c2 = th[0], s2 = th[1];
            float C = c1 * c2 - s1 * s2;
            float S = s1 * c2 + c1 * s2;
            ull tpc = pk(C, C), tpn = pk(-S, S);
            const ull* pr = (const ull*)(aux + OF_PR + l * 64);
            #pragma unroll
            for (int r = 0; r < 16; r++) {
                ull tv = phmul(A[r], tpc, tpn);
                A[r] = phmul(tv, pr[2 * r], pr[2 * r + 1]);
            }
            #pragma unroll
            for (int r = 0; r < 16; r++)
                psi[base_C ^ (r << 2)] = A[r];
            __syncthreads();   // next pass-A gather reads everything
        } else {
            // last layer: phases unobservable; fold CNOT perm + <Z> + head
            #pragma unroll
            for (int r = 0; r < 16; r++) {
                int e = e_baseC | (r << 2);
                int gg = e;
                gg ^= gg >> 1; gg ^= gg >> 2; gg ^= gg >> 4; gg ^= gg >> 8;
                float wt = aux[OF_TLO + (gg & 127)] + aux[OF_THI + ((gg >> 7) & 127)];
                float x, y; upk(A[r], x, y);
                acc = fmaf(fmaf(x, x, y * y), wt, acc);
            }
        }
    }

    // ---- block reduction ----
    #pragma unroll
    for (int o = 16; o; o >>= 1)
        acc += __shfl_xor_sync(0xffffffffu, acc, o);
    if (lane == 0)
        aux[OF_WARP + wa] = acc;
    __syncthreads();
    if (tid < 32) {
        float v = aux[OF_WARP + tid];
        #pragma unroll
        for (int o = 16; o; o >>= 1)
            v += __shfl_xor_sync(0xffffffffu, v, o);
        if (tid == 0)
            out[blockIdx.x] = v + hb[0];
    }
}

extern "C" void kernel_launch(void* const* d_in, const int* in_sizes, int n_in,
                              void* d_out, int out_size)
{
    const float* state = (const float*)d_in[0];
    const float* vp    = (const float*)d_in[1];
    const float* hw    = (const float*)d_in[2];
    const float* hb    = (const float*)d_in[3];
    float* out = (float*)d_out;

    cudaFuncSetAttribute(qsim_kernel,
                         cudaFuncAttributeMaxDynamicSharedMemorySize,
                         (int)SMEM_BYTES);
    qsim_kernel<<<256, THREADS, SMEM_BYTES>>>(state, vp, hw, hb, out);
}

// round 11
// speedup vs baseline: 1.0366x; 1.0366x over previous
#include <cuda_runtime.h>
#include <math.h>

typedef unsigned long long ull;

#define THREADS 1024
#define NSTATE  16384

// aux float offsets (aux = sm + 2*NSTATE floats)
#define OF_GATE 0      // 42 gates * 8 floats: [ca,ca,-sa,-sa,sa,sa,cf,sf]
#define OF_PHI  336    // 42 (phi = 0.5*theta for RZ), padded
#define OF_ENC_C 384   // 14
#define OF_ENC_S 400   // 14
#define OF_RTAB 416    // 16
#define OF_PR   432    // 2 layers * 16 * 4 (wires 8-11, keyed by pass-C r)
#define OF_TL   560    // 2 layers * 32 * 2 (wires 13,12,7,6,5, keyed by pass-C lane)
#define OF_TH   688    // 2 layers * 32 * 2 (wires 4,3,2,1,0, keyed by pass-C wa)
#define OF_TLO  816    // 128
#define OF_THI  944    // 128
#define OF_WARP 1072   // 32
#define AUXF    1104
#define SMEM_BYTES ((2 * NSTATE + AUXF) * sizeof(float))

// Named partial barriers. NEVER id 0 (owned by __syncthreads).
#define BAR_SYNC(id, cnt) \
    asm volatile("bar.sync %0, %1;" :: "r"(id), "r"(cnt) : "memory")

__device__ __forceinline__ ull pk(float lo, float hi) {
    ull r; asm("mov.b64 %0, {%1,%2};" : "=l"(r) : "f"(lo), "f"(hi)); return r;
}
__device__ __forceinline__ void upk(ull v, float& lo, float& hi) {
    asm("mov.b64 {%0,%1}, %2;" : "=f"(lo), "=f"(hi) : "l"(v));
}
__device__ __forceinline__ ull swap2(ull v) {
    float lo, hi;
    asm("mov.b64 {%0,%1}, %2;" : "=f"(lo), "=f"(hi) : "l"(v));
    ull r; asm("mov.b64 %0, {%1,%2};" : "=l"(r) : "f"(hi), "f"(lo)); return r;
}
__device__ __forceinline__ ull mul2(ull a, ull b) {
    ull d; asm("mul.rn.f32x2 %0, %1, %2;" : "=l"(d) : "l"(a), "l"(b)); return d;
}
__device__ __forceinline__ ull fma2(ull a, ull b, ull c) {
    ull d; asm("fma.rn.f32x2 %0, %1, %2, %3;" : "=l"(d) : "l"(a), "l"(b), "l"(c)); return d;
}
// A * e^{i a}: cr2 = (c,c), cn2 = (-s,s)
__device__ __forceinline__ ull phmul(ull A, ull cr2, ull cn2) {
    return fma2(cn2, swap2(A), mul2(cr2, A));
}
__device__ __forceinline__ void pair_ry(ull& A0, ull& A1,
                                        ull ca2, ull nsa2, ull sa2) {
    ull T0 = fma2(nsa2, A1, mul2(ca2, A0));
    ull T1 = fma2(sa2,  A0, mul2(ca2, A1));
    A0 = T0; A1 = T1;
}
__device__ __forceinline__ void shfl_ry(ull& A, unsigned mask, ull ca2, ull sp) {
    ull P = __shfl_xor_sync(0xffffffffu, A, mask);
    A = fma2(sp, P, mul2(ca2, A));
}

__global__ __launch_bounds__(THREADS, 1)
void qsim_kernel(const float* __restrict__ state,   // [256,14]
                 const float* __restrict__ vp,      // [3,14,3]
                 const float* __restrict__ hw,      // [14]
                 const float* __restrict__ hb,      // [1]
                 float* __restrict__ out)           // [256]
{
    extern __shared__ float sm[];
    ull*   psi = (ull*)sm;                 // 16384 packed (re,im), address = h(e)
    float* aux = sm + 2 * NSTATE;

    const int tid  = threadIdx.x;
    const int lane = tid & 31;
    const int wa   = tid >> 5;

    // ---- setup stage 1 ----
    if (tid < 42) {
        float a  = 0.5f * vp[tid * 3 + 0];
        float th = 0.5f * vp[tid * 3 + 1];
        float ca, sa, cf, sf;
        sincosf(a,  &sa, &ca);
        sincosf(th, &sf, &cf);
        float* g = aux + OF_GATE + tid * 8;
        g[0] = ca;  g[1] = ca;
        g[2] = -sa; g[3] = -sa;
        g[4] = sa;  g[5] = sa;
        g[6] = cf;  g[7] = sf;
        aux[OF_PHI + tid] = th;
    } else if (tid >= 64 && tid < 78) {
        int w = tid - 64;
        float h = 0.5f * state[blockIdx.x * 14 + w];
        float c, s;
        sincosf(h, &s, &c);
        aux[OF_ENC_C + w] = c;
        aux[OF_ENC_S + w] = s;
    } else if (tid >= 128 && tid < 256) {
        int x = tid - 128;
        float a2 = 0.f;
        #pragma unroll
        for (int p = 0; p < 7; p++)
            a2 += (((x >> p) & 1) ? -1.f : 1.f) * hw[13 - p];
        aux[OF_TLO + x] = a2;
    } else if (tid >= 256 && tid < 384) {
        int x = tid - 256;
        float a2 = 0.f;
        #pragma unroll
        for (int p = 0; p < 7; p++)
            a2 += (((x >> p) & 1) ? -1.f : 1.f) * hw[6 - p];
        aux[OF_THI + x] = a2;
    }
    __syncthreads();

    // ---- setup stage 2 ----
    if (tid < 16) {
        float m = 1.f;
        #pragma unroll
        for (int j = 0; j < 4; j++)
            m *= ((tid >> j) & 1) ? aux[OF_ENC_S + 3 - j] : aux[OF_ENC_C + 3 - j];
        aux[OF_RTAB + tid] = m;
    } else if (tid >= 32 && tid < 64) {
        // PR: wires 8-11 phase, keyed by pass-C r
        int idx = tid - 32;
        int l = idx >> 4, r = idx & 15;
        const float* ph = aux + OF_PHI + l * 14;
        float ang = (( r       & 1) ? ph[11] : -ph[11])
                  + (((r >> 1) & 1) ? ph[10] : -ph[10])
                  + (((r >> 2) & 1) ? ph[9]  : -ph[9])
                  + (((r >> 3) & 1) ? ph[8]  : -ph[8]);
        float c, s;
        sincosf(ang, &s, &c);
        float* p = aux + OF_PR + (l * 16 + r) * 4;
        p[0] = c; p[1] = c; p[2] = -s; p[3] = s;
    } else if (tid >= 64 && tid < 128) {
        // TL: pass-C lane bits -> wires 13,12,7,6,5
        int idx = tid - 64;
        int l = idx >> 5, ln = idx & 31;
        const float* ph = aux + OF_PHI + l * 14;
        float ang = (( ln       & 1) ? ph[13] : -ph[13])
                  + (((ln >> 1) & 1) ? ph[12] : -ph[12])
                  + (((ln >> 2) & 1) ? ph[7]  : -ph[7])
                  + (((ln >> 3) & 1) ? ph[6]  : -ph[6])
                  + (((ln >> 4) & 1) ? ph[5]  : -ph[5]);
        float c, s;
        sincosf(ang, &s, &c);
        aux[OF_TL + (l * 32 + ln) * 2]     = c;
        aux[OF_TL + (l * 32 + ln) * 2 + 1] = s;
    } else if (tid >= 128 && tid < 192) {
        // TH: pass-C wa bits -> wires 4,3,2,1,0
        int idx = tid - 128;
        int l = idx >> 5, w5 = idx & 31;
        const float* ph = aux + OF_PHI + l * 14;
        float ang = (( w5       & 1) ? ph[4] : -ph[4])
                  + (((w5 >> 1) & 1) ? ph[3] : -ph[3])
                  + (((w5 >> 2) & 1) ? ph[2] : -ph[2])
                  + (((w5 >> 3) & 1) ? ph[1] : -ph[1])
                  + (((w5 >> 4) & 1) ? ph[0] : -ph[0]);
        float c, s;
        sincosf(ang, &s, &c);
        aux[OF_TH + (l * 32 + w5) * 2]     = c;
        aux[OF_TH + (l * 32 + w5) * 2 + 1] = s;
    }
    // per-thread RX base product over tid bits 0..9 (wires 13..4)
    float P = 1.f;
    #pragma unroll
    for (int j = 0; j < 10; j++)
        P *= ((tid >> j) & 1) ? aux[OF_ENC_S + 13 - j] : aux[OF_ENC_C + 13 - j];
    int pt = __popc(tid);
    __syncthreads();

    // ---- init directly in pass-A register layout: e = tid | (r<<10) ----
    ull A[16];
    #pragma unroll
    for (int r = 0; r < 16; r++) {
        float mag = P * aux[OF_RTAB + r];
        int k = (pt + __popc(r)) & 3;
        float sg = (k == 1 || k == 2) ? -mag : mag;
        float re_ = (k & 1) ? 0.f : sg;
        float im_ = (k & 1) ? sg : 0.f;
        A[r] = pk(re_, im_);
    }

    float acc = 0.f;

    // ---- address bases under global map h(e) = e ^ (((e>>6)&7)<<2) ----
    const int baseA_st = tid ^ (((tid >> 6) & 7) << 2);
    const int gt = tid ^ (tid >> 1);
    const int baseA_ld = gt ^ (((gt >> 6) & 7) << 2);
    const int base_B = lane | ((wa & 1) << 5) | ((wa >> 1) << 10);
    const int eC_hi = (((lane >> 2) & 7) << 6) | (wa << 9);
    const int base_C = ((lane & 3) | eC_hi) ^ (((lane >> 2) & 7) << 2);
    const int e_baseC = (lane & 3) | eC_hi;

    // group-barrier ids (never 0): A->B parity = 5+(wa&1) cnt 512;
    // B->C octet = 1+(wa>>3) cnt 256 (superset of the {2k,2k+1} writer pair)
    const int barAB = 5 + (wa & 1);
    const int barBC = 1 + (wa >> 3);

    #pragma unroll 1          // keep code small: I$ blowup was the R9 regression
    for (int l = 0; l < 3; l++) {
        // ======== Pass A: wires 0-3 pair (r bits), wires 12,13 shfl ========
        if (l) {
            #pragma unroll
            for (int r = 0; r < 16; r++)
                A[r] = psi[baseA_ld ^ (((r ^ (r << 1)) & 31) << 9)];
            __syncthreads();   // gather set != scatter set
        }
        #pragma unroll
        for (int w = 12; w < 14; w++) {
            const ull* g = (const ull*)(aux + OF_GATE + (l * 14 + w) * 8);
            int bit = 13 - w;
            ull ca2 = g[0];
            ull sp  = ((lane >> bit) & 1) ? g[2] : g[1];
            unsigned mask = 1u << bit;
            #pragma unroll
            for (int r = 0; r < 16; r++)
                shfl_ry(A[r], mask, ca2, sp);
        }
        #pragma unroll
        for (int w = 0; w < 4; w++) {
            const ull* g = (const ull*)(aux + OF_GATE + (l * 14 + w) * 8);
            ull ca2 = g[0], nsa2 = g[1], sa2 = g[2];
            int bj = 1 << (3 - w);
            #pragma unroll
            for (int r = 0; r < 16; r++)
                if (!(r & bj))
                    pair_ry(A[r], A[r | bj], ca2, nsa2, sa2);
        }
        #pragma unroll
        for (int r = 0; r < 16; r++)
            psi[baseA_st | (r << 10)] = A[r];
        BAR_SYNC(barAB, 512);   // B reads only same-parity A-writers

        // ======== Pass B: wires 4-7 pair ========
        #pragma unroll
        for (int r = 0; r < 16; r++)
            A[r] = psi[base_B ^ ((r << 6) | ((r & 7) << 2))];
        #pragma unroll
        for (int w = 4; w < 8; w++) {
            const ull* g = (const ull*)(aux + OF_GATE + (l * 14 + w) * 8);
            ull ca2 = g[0], nsa2 = g[1], sa2 = g[2];
            int bj = 1 << (7 - w);
            #pragma unroll
            for (int r = 0; r < 16; r++)
                if (!(r & bj))
                    pair_ry(A[r], A[r | bj], ca2, nsa2, sa2);
        }
        #pragma unroll
        for (int r = 0; r < 16; r++)
            psi[base_B ^ ((r << 6) | ((r & 7) << 2))] = A[r];
        BAR_SYNC(barBC, 256);   // C reads only from its B warp-pair (in-octet)

        // ======== Pass C: wires 8-11 pair ========
        #pragma unroll
        for (int r = 0; r < 16; r++)
            A[r] = psi[base_C ^ (r << 2)];
        #pragma unroll
        for (int w = 8; w < 12; w++) {
            const ull* g = (const ull*)(aux + OF_GATE + (l * 14 + w) * 8);
            ull ca2 = g[0], nsa2 = g[1], sa2 = g[2];
            int bj = 1 << (11 - w);
            #pragma unroll
            for (int r = 0; r < 16; r++)
                if (!(r & bj))
                    pair_ry(A[r], A[r | bj], ca2, nsa2, sa2);
        }

        if (l < 2) {
            // ---- all 14 wires' RZ phases once: TL[lane]*TH[wa]*PR[r] ----
            const float* tl = aux + OF_TL + (l * 32 + lane) * 2;
            const float* th = aux + OF_TH + (l * 32 + wa) * 2;
            float c1 = tl[0], s1 = tl[1], c2 = th[0], s2 = th[1];
            float C = c1 * c2 - s1 * s2;
            float S = s1 * c2 + c1 * s2;
            ull tpc = pk(C, C), tpn = pk(-S, S);
            const ull* pr = (const ull*)(aux + OF_PR + l * 64);
            #pragma unroll
            for (int r = 0; r < 16; r++) {
                ull tv = phmul(A[r], tpc, tpn);
                A[r] = phmul(tv, pr[2 * r], pr[2 * r + 1]);
            }
            #pragma unroll
            for (int r = 0; r < 16; r++)
                psi[base_C ^ (r << 2)] = A[r];
            __syncthreads();   // next pass-A gather reads everything
        } else {
            // last layer: phases unobservable; fold CNOT perm + <Z> + head
            #pragma unroll
            for (int r = 0; r < 16; r++) {
                int e = e_baseC | (r << 2);
                int gg = e;
                gg ^= gg >> 1; gg ^= gg >> 2; gg ^= gg >> 4; gg ^= gg >> 8;
                float wt = aux[OF_TLO + (gg & 127)] + aux[OF_THI + ((gg >> 7) & 127)];
                float x, y; upk(A[r], x, y);
                acc = fmaf(fmaf(x, x, y * y), wt, acc);
            }
        }
    }

    // ---- block reduction ----
    #pragma unroll
    for (int o = 16; o; o >>= 1)
        acc += __shfl_xor_sync(0xffffffffu, acc, o);
    if (lane == 0)
        aux[OF_WARP + wa] = acc;
    __syncthreads();
    if (tid < 32) {
        float v = aux[OF_WARP + tid];
        #pragma unroll
        for (int o = 16; o; o >>= 1)
            v += __shfl_xor_sync(0xffffffffu, v, o);
        if (tid == 0)
            out[blockIdx.x] = v + hb[0];
    }
}

extern "C" void kernel_launch(void* const* d_in, const int* in_sizes, int n_in,
                              void* d_out, int out_size)
{
    const float* state = (const float*)d_in[0];
    const float* vp    = (const float*)d_in[1];
    const float* hw    = (const float*)d_in[2];
    const float* hb    = (const float*)d_in[3];
    float* out = (float*)d_out;

    cudaFuncSetAttribute(qsim_kernel,
                         cudaFuncAttributeMaxDynamicSharedMemorySize,
                         (int)SMEM_BYTES);
    qsim_kernel<<<256, THREADS, SMEM_BYTES>>>(state, vp, hw, hb, out);
}

// round 13
// speedup vs baseline: 1.0728x; 1.0350x over previous
#include <cuda_runtime.h>
#include <math.h>

typedef unsigned long long ull;

#define THREADS 1024
#define NSTATE  16384

// aux float offsets (aux = sm + 2*NSTATE floats)
#define OF_GATE 0      // 42 gates * 8 floats: [ca,ca,-sa,-sa,sa,sa,cf,sf]
#define OF_PHI  336    // 42 (phi = 0.5*theta for RZ), padded
#define OF_ENC_C 384   // 14
#define OF_ENC_S 400   // 14
#define OF_RTAB 416    // 16
#define OF_PR   432    // 2 layers * 16 * 4 (wires 8-11, keyed by pass-C r)
#define OF_TL   560    // 2 layers * 32 * 2 (wires 13,12,7,6,5, keyed by pass-C lane)
#define OF_TH   688    // 2 layers * 32 * 2 (wires 4,3,2,1,0, keyed by pass-C wa)
#define OF_TLO  816    // 128
#define OF_THI  944    // 128
#define OF_WARP 1072   // 32
#define AUXF    1104
#define SMEM_BYTES ((2 * NSTATE + AUXF) * sizeof(float))

// global bank hash: h(x) = x ^ (x7<<2) ^ ((x6^x7^x8)<<3) ^ (x8<<4)
__device__ __forceinline__ int hmap(int x) {
    int b6 = (x >> 6) & 1, b7 = (x >> 7) & 1, b8 = (x >> 8) & 1;
    return x ^ (b7 << 2) ^ ((b6 ^ b7 ^ b8) << 3) ^ (b8 << 4);
}
// gray decode of (r<<2), bits 0-5 only (compile-time for literal r)
__device__ __forceinline__ constexpr int dgray4(int r) {
    int x = r << 2;
    return x ^ (x >> 1) ^ (x >> 2) ^ (x >> 3) ^ (x >> 4) ^ (x >> 5);
}
// pass-B swizzle for register index r (x bits 6-8 = r bits 0-2)
__device__ __forceinline__ constexpr int swb(int r) {
    int r0 = r & 1, r1 = (r >> 1) & 1, r2 = (r >> 2) & 1;
    return (r1 << 2) | ((r0 ^ r1 ^ r2) << 3) | (r2 << 4);
}

__device__ __forceinline__ ull pk(float lo, float hi) {
    ull r; asm("mov.b64 %0, {%1,%2};" : "=l"(r) : "f"(lo), "f"(hi)); return r;
}
__device__ __forceinline__ void upk(ull v, float& lo, float& hi) {
    asm("mov.b64 {%0,%1}, %2;" : "=f"(lo), "=f"(hi) : "l"(v));
}
__device__ __forceinline__ ull swap2(ull v) {
    float lo, hi;
    asm("mov.b64 {%0,%1}, %2;" : "=f"(lo), "=f"(hi) : "l"(v));
    ull r; asm("mov.b64 %0, {%1,%2};" : "=l"(r) : "f"(hi), "f"(lo)); return r;
}
__device__ __forceinline__ ull mul2(ull a, ull b) {
    ull d; asm("mul.rn.f32x2 %0, %1, %2;" : "=l"(d) : "l"(a), "l"(b)); return d;
}
__device__ __forceinline__ ull fma2(ull a, ull b, ull c) {
    ull d; asm("fma.rn.f32x2 %0, %1, %2, %3;" : "=l"(d) : "l"(a), "l"(b), "l"(c)); return d;
}
// A * e^{i a}: cr2 = (c,c), cn2 = (-s,s)
__device__ __forceinline__ ull phmul(ull A, ull cr2, ull cn2) {
    return fma2(cn2, swap2(A), mul2(cr2, A));
}
__device__ __forceinline__ void pair_ry(ull& A0, ull& A1,
                                        ull ca2, ull nsa2, ull sa2) {
    ull T0 = fma2(nsa2, A1, mul2(ca2, A0));
    ull T1 = fma2(sa2,  A0, mul2(ca2, A1));
    A0 = T0; A1 = T1;
}
__device__ __forceinline__ void shfl_ry(ull& A, unsigned mask, ull ca2, ull sp) {
    ull P = __shfl_xor_sync(0xffffffffu, A, mask);
    A = fma2(sp, P, mul2(ca2, A));
}

__global__ __launch_bounds__(THREADS, 1)
void qsim_kernel(const float* __restrict__ state,   // [256,14]
                 const float* __restrict__ vp,      // [3,14,3]
                 const float* __restrict__ hw,      // [14]
                 const float* __restrict__ hb,      // [1]
                 float* __restrict__ out)           // [256]
{
    extern __shared__ float sm[];
    ull*   psi = (ull*)sm;                 // 16384 packed (re,im), slot = hmap(idx)
    float* aux = sm + 2 * NSTATE;

    const int tid  = threadIdx.x;
    const int lane = tid & 31;
    const int wa   = tid >> 5;

    // ---- setup stage 1 ----
    if (tid < 42) {
        float a  = 0.5f * vp[tid * 3 + 0];
        float th = 0.5f * vp[tid * 3 + 1];
        float ca, sa, cf, sf;
        sincosf(a,  &sa, &ca);
        sincosf(th, &sf, &cf);
        float* g = aux + OF_GATE + tid * 8;
        g[0] = ca;  g[1] = ca;
        g[2] = -sa; g[3] = -sa;
        g[4] = sa;  g[5] = sa;
        g[6] = cf;  g[7] = sf;
        aux[OF_PHI + tid] = th;
    } else if (tid >= 64 && tid < 78) {
        int w = tid - 64;
        float h = 0.5f * state[blockIdx.x * 14 + w];
        float c, s;
        sincosf(h, &s, &c);
        aux[OF_ENC_C + w] = c;
        aux[OF_ENC_S + w] = s;
    } else if (tid >= 128 && tid < 256) {
        int x = tid - 128;
        float a2 = 0.f;
        #pragma unroll
        for (int p = 0; p < 7; p++)
            a2 += (((x >> p) & 1) ? -1.f : 1.f) * hw[13 - p];
        aux[OF_TLO + x] = a2;
    } else if (tid >= 256 && tid < 384) {
        int x = tid - 256;
        float a2 = 0.f;
        #pragma unroll
        for (int p = 0; p < 7; p++)
            a2 += (((x >> p) & 1) ? -1.f : 1.f) * hw[6 - p];
        aux[OF_THI + x] = a2;
    }
    __syncthreads();

    // ---- setup stage 2 ----
    if (tid < 16) {
        float m = 1.f;
        #pragma unroll
        for (int j = 0; j < 4; j++)
            m *= ((tid >> j) & 1) ? aux[OF_ENC_S + 3 - j] : aux[OF_ENC_C + 3 - j];
        aux[OF_RTAB + tid] = m;
    } else if (tid >= 32 && tid < 64) {
        // PR: wires 8-11 phase, keyed by pass-C r
        int idx = tid - 32;
        int l = idx >> 4, r = idx & 15;
        const float* ph = aux + OF_PHI + l * 14;
        float ang = (( r       & 1) ? ph[11] : -ph[11])
                  + (((r >> 1) & 1) ? ph[10] : -ph[10])
                  + (((r >> 2) & 1) ? ph[9]  : -ph[9])
                  + (((r >> 3) & 1) ? ph[8]  : -ph[8]);
        float c, s;
        sincosf(ang, &s, &c);
        float* p = aux + OF_PR + (l * 16 + r) * 4;
        p[0] = c; p[1] = c; p[2] = -s; p[3] = s;
    } else if (tid >= 64 && tid < 128) {
        // TL: pass-C lane bits -> wires 13,12,7,6,5
        int idx = tid - 64;
        int l = idx >> 5, ln = idx & 31;
        const float* ph = aux + OF_PHI + l * 14;
        float ang = (( ln       & 1) ? ph[13] : -ph[13])
                  + (((ln >> 1) & 1) ? ph[12] : -ph[12])
                  + (((ln >> 2) & 1) ? ph[7]  : -ph[7])
                  + (((ln >> 3) & 1) ? ph[6]  : -ph[6])
                  + (((ln >> 4) & 1) ? ph[5]  : -ph[5]);
        float c, s;
        sincosf(ang, &s, &c);
        aux[OF_TL + (l * 32 + ln) * 2]     = c;
        aux[OF_TL + (l * 32 + ln) * 2 + 1] = s;
    } else if (tid >= 128 && tid < 192) {
        // TH: pass-C wa bits -> wires 4,3,2,1,0
        int idx = tid - 128;
        int l = idx >> 5, w5 = idx & 31;
        const float* ph = aux + OF_PHI + l * 14;
        float ang = (( w5       & 1) ? ph[4] : -ph[4])
                  + (((w5 >> 1) & 1) ? ph[3] : -ph[3])
                  + (((w5 >> 2) & 1) ? ph[2] : -ph[2])
                  + (((w5 >> 3) & 1) ? ph[1] : -ph[1])
                  + (((w5 >> 4) & 1) ? ph[0] : -ph[0]);
        float c, s;
        sincosf(ang, &s, &c);
        aux[OF_TH + (l * 32 + w5) * 2]     = c;
        aux[OF_TH + (l * 32 + w5) * 2 + 1] = s;
    }
    // per-thread RX base product over tid bits 0..9 (wires 13..4)
    float P = 1.f;
    #pragma unroll
    for (int j = 0; j < 10; j++)
        P *= ((tid >> j) & 1) ? aux[OF_ENC_S + 13 - j] : aux[OF_ENC_C + 13 - j];
    int pt = __popc(tid);
    __syncthreads();

    // ---- init directly in pass-A register layout: e = tid | (r<<10) ----
    ull A[16];
    #pragma unroll
    for (int r = 0; r < 16; r++) {
        float mag = P * aux[OF_RTAB + r];
        int k = (pt + __popc(r)) & 3;
        float sg = (k == 1 || k == 2) ? -mag : mag;
        float re_ = (k & 1) ? 0.f : sg;
        float im_ = (k & 1) ? sg : 0.f;
        A[r] = pk(re_, im_);
    }

    float acc = 0.f;

    // ---- per-pass address bases under hash hmap ----
    const int baseA = hmap(tid);                    // A: addr = baseA | (r<<10)
    const int base_B0 = lane | ((wa & 1) << 5) | ((wa >> 1) << 10);  // bits 6-8 zero
    const int e_baseC = (lane & 3) | (((lane >> 2) & 7) << 6) | (wa << 9);
    const int base_C = hmap(e_baseC);               // C load: addr = base_C ^ (r<<2)
    // C store (gray-perm folded): y = D(e); addr = hmap(D(e_baseC)) ^ dgray4(r)
    int dC = e_baseC;
    dC ^= dC >> 1; dC ^= dC >> 2; dC ^= dC >> 4; dC ^= dC >> 8;
    const int ybase = hmap(dC);

    #pragma unroll 1          // keep code small (I$: R9 lesson)
    for (int l = 0; l < 3; l++) {
        // ======== Pass A: wires 0-3 pair (r bits), wires 12,13 shfl ========
        if (l) {
            // state already gray-permuted by pass C's scatter: linear load,
            // read-set == write-set per thread -> NO barrier needed here
            #pragma unroll
            for (int r = 0; r < 16; r++)
                A[r] = psi[baseA | (r << 10)];
        }
        #pragma unroll
        for (int w = 12; w < 14; w++) {
            const ull* g = (const ull*)(aux + OF_GATE + (l * 14 + w) * 8);
            int bit = 13 - w;
            ull ca2 = g[0];
            ull sp  = ((lane >> bit) & 1) ? g[2] : g[1];
            unsigned mask = 1u << bit;
            #pragma unroll
            for (int r = 0; r < 16; r++)
                shfl_ry(A[r], mask, ca2, sp);
        }
        #pragma unroll
        for (int w = 0; w < 4; w++) {
            const ull* g = (const ull*)(aux + OF_GATE + (l * 14 + w) * 8);
            ull ca2 = g[0], nsa2 = g[1], sa2 = g[2];
            int bj = 1 << (3 - w);
            #pragma unroll
            for (int r = 0; r < 16; r++)
                if (!(r & bj))
                    pair_ry(A[r], A[r | bj], ca2, nsa2, sa2);
        }
        #pragma unroll
        for (int r = 0; r < 16; r++)
            psi[baseA | (r << 10)] = A[r];
        __syncthreads();

        // ======== Pass B: wires 4-7 pair ========
        #pragma unroll
        for (int r = 0; r < 16; r++)
            A[r] = psi[base_B0 ^ ((r << 6) | swb(r))];
        #pragma unroll
        for (int w = 4; w < 8; w++) {
            const ull* g = (const ull*)(aux + OF_GATE + (l * 14 + w) * 8);
            ull ca2 = g[0], nsa2 = g[1], sa2 = g[2];
            int bj = 1 << (7 - w);
            #pragma unroll
            for (int r = 0; r < 16; r++)
                if (!(r & bj))
                    pair_ry(A[r], A[r | bj], ca2, nsa2, sa2);
        }
        #pragma unroll
        for (int r = 0; r < 16; r++)
            psi[base_B0 ^ ((r << 6) | swb(r))] = A[r];
        __syncthreads();

        // ======== Pass C: wires 8-11 pair ========
        #pragma unroll
        for (int r = 0; r < 16; r++)
            A[r] = psi[base_C ^ (r << 2)];
        #pragma unroll
        for (int w = 8; w < 12; w++) {
            const ull* g = (const ull*)(aux + OF_GATE + (l * 14 + w) * 8);
            ull ca2 = g[0], nsa2 = g[1], sa2 = g[2];
            int bj = 1 << (11 - w);
            #pragma unroll
            for (int r = 0; r < 16; r++)
                if (!(r & bj))
                    pair_ry(A[r], A[r | bj], ca2, nsa2, sa2);
        }

        if (l < 2) {
            // ---- all 14 wires' RZ phases once: TL[lane]*TH[wa]*PR[r] ----
            const float* tl = aux + OF_TL + (l * 32 + lane) * 2;
            const float* th = aux + OF_TH + (l * 32 + wa) * 2;
            float c1 = tl[0], s1 = tl[1], c2 = th[0], s2 = th[1];
            float C = c1 * c2 - s1 * s2;
            float S = s1 * c2 + c1 * s2;
            ull tpc = pk(C, C), tpn = pk(-S, S);
            const ull* pr = (const ull*)(aux + OF_PR + l * 64);
            #pragma unroll
            for (int r = 0; r < 16; r++) {
                ull tv = phmul(A[r], tpc, tpn);
                A[r] = phmul(tv, pr[2 * r], pr[2 * r + 1]);
            }
            // ---- scatter with CNOT gray-perm folded in: slot h(D(e)) ----
            #pragma unroll
            for (int r = 0; r < 16; r++)
                psi[ybase ^ dgray4(r)] = A[r];
            __syncthreads();
        } else {
            // last layer: phases unobservable; fold final perm + <Z> + head
            #pragma unroll
            for (int r = 0; r < 16; r++) {
                int e = e_baseC | (r << 2);
                int gg = e;
                gg ^= gg >> 1; gg ^= gg >> 2; gg ^= gg >> 4; gg ^= gg >> 8;
                float wt = aux[OF_TLO + (gg & 127)] + aux[OF_THI + ((gg >> 7) & 127)];
                float x, y; upk(A[r], x, y);
                acc = fmaf(fmaf(x, x, y * y), wt, acc);
            }
        }
    }

    // ---- block reduction ----
    #pragma unroll
    for (int o = 16; o; o >>= 1)
        acc += __shfl_xor_sync(0xffffffffu, acc, o);
    if (lane == 0)
        aux[OF_WARP + wa] = acc;
    __syncthreads();
    if (tid < 32) {
        float v = aux[OF_WARP + tid];
        #pragma unroll
        for (int o = 16; o; o >>= 1)
            v += __shfl_xor_sync(0xffffffffu, v, o);
        if (tid == 0)
            out[blockIdx.x] = v + hb[0];
    }
}

extern "C" void kernel_launch(void* const* d_in, const int* in_sizes, int n_in,
                              void* d_out, int out_size)
{
    const float* state = (const float*)d_in[0];
    const float* vp    = (const float*)d_in[1];
    const float* hw    = (const float*)d_in[2];
    const float* hb    = (const float*)d_in[3];
    float* out = (float*)d_out;

    cudaFuncSetAttribute(qsim_kernel,
                         cudaFuncAttributeMaxDynamicSharedMemorySize,
                         (int)SMEM_BYTES);
    qsim_kernel<<<256, THREADS, SMEM_BYTES>>>(state, vp, hw, hb, out);
}

// round 14
// speedup vs baseline: 1.1528x; 1.0746x over previous
#include <cuda_runtime.h>
#include <math.h>

typedef unsigned long long ull;

#define THREADS 1024
#define NSTATE  16384
#define NSAMP   256
#define GRID    148

// aux float offsets (aux = sm + 2*NSTATE floats)
#define OF_GATE 0      // 42 gates * 8 floats: [ca,ca,-sa,-sa,sa,sa,cf,sf]
#define OF_PHI  336    // 42 (phi = 0.5*theta for RZ), padded
#define OF_ENC_C 384   // 14
#define OF_ENC_S 400   // 14
#define OF_RTAB 416    // 16
#define OF_PR   432    // 2 layers * 16 * 4 (wires 8-11, keyed by pass-C r)
#define OF_TL   560    // 2 layers * 32 * 2 (wires 13,12,7,6,5, keyed by pass-C lane)
#define OF_TH   688    // 2 layers * 32 * 2 (wires 4,3,2,1,0, keyed by pass-C wa)
#define OF_TLO  816    // 128
#define OF_THI  944    // 128
#define OF_WARP 1072   // 32
#define AUXF    1104
#define SMEM_BYTES ((2 * NSTATE + AUXF) * sizeof(float))

// gray-decode of (r<<2) restricted to its bit span (compile-time for literal r)
__device__ __forceinline__ constexpr int dgray4(int r) {
    int x = r << 2;
    return x ^ (x >> 1) ^ (x >> 2) ^ (x >> 3) ^ (x >> 4) ^ (x >> 5);
}

__device__ __forceinline__ ull pk(float lo, float hi) {
    ull r; asm("mov.b64 %0, {%1,%2};" : "=l"(r) : "f"(lo), "f"(hi)); return r;
}
__device__ __forceinline__ void upk(ull v, float& lo, float& hi) {
    asm("mov.b64 {%0,%1}, %2;" : "=f"(lo), "=f"(hi) : "l"(v));
}
__device__ __forceinline__ ull swap2(ull v) {
    float lo, hi;
    asm("mov.b64 {%0,%1}, %2;" : "=f"(lo), "=f"(hi) : "l"(v));
    ull r; asm("mov.b64 %0, {%1,%2};" : "=l"(r) : "f"(hi), "f"(lo)); return r;
}
__device__ __forceinline__ ull mul2(ull a, ull b) {
    ull d; asm("mul.rn.f32x2 %0, %1, %2;" : "=l"(d) : "l"(a), "l"(b)); return d;
}
__device__ __forceinline__ ull fma2(ull a, ull b, ull c) {
    ull d; asm("fma.rn.f32x2 %0, %1, %2, %3;" : "=l"(d) : "l"(a), "l"(b), "l"(c)); return d;
}
// A * e^{i a}: cr2 = (c,c), cn2 = (-s,s)
__device__ __forceinline__ ull phmul(ull A, ull cr2, ull cn2) {
    return fma2(cn2, swap2(A), mul2(cr2, A));
}
__device__ __forceinline__ void pair_ry(ull& A0, ull& A1,
                                        ull ca2, ull nsa2, ull sa2) {
    ull T0 = fma2(nsa2, A1, mul2(ca2, A0));
    ull T1 = fma2(sa2,  A0, mul2(ca2, A1));
    A0 = T0; A1 = T1;
}
__device__ __forceinline__ void shfl_ry(ull& A, unsigned mask, ull ca2, ull sp) {
    ull P = __shfl_xor_sync(0xffffffffu, A, mask);
    A = fma2(sp, P, mul2(ca2, A));
}

__global__ __launch_bounds__(THREADS, 1)
void qsim_kernel(const float* __restrict__ state,   // [256,14]
                 const float* __restrict__ vp,      // [3,14,3]
                 const float* __restrict__ hw,      // [14]
                 const float* __restrict__ hb,      // [1]
                 float* __restrict__ out)           // [256]
{
    extern __shared__ float sm[];
    ull*   psi = (ull*)sm;                 // 16384 packed (re,im), slot = h(e)
    float* aux = sm + 2 * NSTATE;

    const int tid  = threadIdx.x;
    const int lane = tid & 31;
    const int wa   = tid >> 5;

    // ================= sample-independent setup (ONCE per CTA) =================
    if (tid < 42) {
        float a  = 0.5f * vp[tid * 3 + 0];
        float th = 0.5f * vp[tid * 3 + 1];
        float ca, sa, cf, sf;
        sincosf(a,  &sa, &ca);
        sincosf(th, &sf, &cf);
        float* g = aux + OF_GATE + tid * 8;
        g[0] = ca;  g[1] = ca;
        g[2] = -sa; g[3] = -sa;
        g[4] = sa;  g[5] = sa;
        g[6] = cf;  g[7] = sf;
        aux[OF_PHI + tid] = th;
    } else if (tid >= 128 && tid < 256) {
        int x = tid - 128;
        float a2 = 0.f;
        #pragma unroll
        for (int p = 0; p < 7; p++)
            a2 += (((x >> p) & 1) ? -1.f : 1.f) * hw[13 - p];
        aux[OF_TLO + x] = a2;
    } else if (tid >= 256 && tid < 384) {
        int x = tid - 256;
        float a2 = 0.f;
        #pragma unroll
        for (int p = 0; p < 7; p++)
            a2 += (((x >> p) & 1) ? -1.f : 1.f) * hw[6 - p];
        aux[OF_THI + x] = a2;
    }
    __syncthreads();

    if (tid >= 32 && tid < 64) {
        // PR: wires 8-11 phase, keyed by pass-C r
        int idx = tid - 32;
        int l = idx >> 4, r = idx & 15;
        const float* ph = aux + OF_PHI + l * 14;
        float ang = (( r       & 1) ? ph[11] : -ph[11])
                  + (((r >> 1) & 1) ? ph[10] : -ph[10])
                  + (((r >> 2) & 1) ? ph[9]  : -ph[9])
                  + (((r >> 3) & 1) ? ph[8]  : -ph[8]);
        float c, s;
        sincosf(ang, &s, &c);
        float* p = aux + OF_PR + (l * 16 + r) * 4;
        p[0] = c; p[1] = c; p[2] = -s; p[3] = s;
    } else if (tid >= 64 && tid < 128) {
        // TL: pass-C lane bits -> wires 13,12,7,6,5
        int idx = tid - 64;
        int l = idx >> 5, ln = idx & 31;
        const float* ph = aux + OF_PHI + l * 14;
        float ang = (( ln       & 1) ? ph[13] : -ph[13])
                  + (((ln >> 1) & 1) ? ph[12] : -ph[12])
                  + (((ln >> 2) & 1) ? ph[7]  : -ph[7])
                  + (((ln >> 3) & 1) ? ph[6]  : -ph[6])
                  + (((ln >> 4) & 1) ? ph[5]  : -ph[5]);
        float c, s;
        sincosf(ang, &s, &c);
        aux[OF_TL + (l * 32 + ln) * 2]     = c;
        aux[OF_TL + (l * 32 + ln) * 2 + 1] = s;
    } else if (tid >= 128 && tid < 192) {
        // TH: pass-C wa bits -> wires 4,3,2,1,0
        int idx = tid - 128;
        int l = idx >> 5, w5 = idx & 31;
        const float* ph = aux + OF_PHI + l * 14;
        float ang = (( w5       & 1) ? ph[4] : -ph[4])
                  + (((w5 >> 1) & 1) ? ph[3] : -ph[3])
                  + (((w5 >> 2) & 1) ? ph[2] : -ph[2])
                  + (((w5 >> 3) & 1) ? ph[1] : -ph[1])
                  + (((w5 >> 4) & 1) ? ph[0] : -ph[0]);
        float c, s;
        sincosf(ang, &s, &c);
        aux[OF_TH + (l * 32 + w5) * 2]     = c;
        aux[OF_TH + (l * 32 + w5) * 2 + 1] = s;
    }

    // ---- address bases under map h(e) = e ^ (((e>>6)&7)<<2) (R8 scheme) ----
    const int baseA_st = tid ^ (((tid >> 6) & 7) << 2);
    const int gt = tid ^ (tid >> 1);
    const int baseA_ld = gt ^ (((gt >> 6) & 7) << 2);
    const int base_B = lane | ((wa & 1) << 5) | ((wa >> 1) << 10);
    const int eC_hi = (((lane >> 2) & 7) << 6) | (wa << 9);
    const int base_C = ((lane & 3) | eC_hi) ^ (((lane >> 2) & 7) << 2);
    const int e_baseC = (lane & 3) | eC_hi;
    // epilogue: gg = D(e_baseC) ^ DT[r], DT compile-time (D linear, disjoint bits)
    int ggB = e_baseC;
    ggB ^= ggB >> 1; ggB ^= ggB >> 2; ggB ^= ggB >> 4; ggB ^= ggB >> 8;

    // ================= per-sample loop (persistent CTA) =================
    #pragma unroll 1
    for (int s = blockIdx.x; s < NSAMP; s += GRID) {
        __syncthreads();   // tables ready (first iter) / prev sample done

        // per-sample encoding angles
        if (tid < 14) {
            float h = 0.5f * state[s * 14 + tid];
            float c, ss;
            sincosf(h, &ss, &c);
            aux[OF_ENC_C + tid] = c;
            aux[OF_ENC_S + tid] = ss;
        }
        __syncthreads();
        if (tid < 16) {
            float m = 1.f;
            #pragma unroll
            for (int j = 0; j < 4; j++)
                m *= ((tid >> j) & 1) ? aux[OF_ENC_S + 3 - j] : aux[OF_ENC_C + 3 - j];
            aux[OF_RTAB + tid] = m;
        }
        float P = 1.f;
        #pragma unroll
        for (int j = 0; j < 10; j++)
            P *= ((tid >> j) & 1) ? aux[OF_ENC_S + 13 - j] : aux[OF_ENC_C + 13 - j];
        int pt = __popc(tid);
        __syncthreads();

        // ---- init directly in pass-A register layout: e = tid | (r<<10) ----
        ull A[16];
        #pragma unroll
        for (int r = 0; r < 16; r++) {
            float mag = P * aux[OF_RTAB + r];
            int k = (pt + __popc(r)) & 3;
            float sg = (k == 1 || k == 2) ? -mag : mag;
            float re_ = (k & 1) ? 0.f : sg;
            float im_ = (k & 1) ? sg : 0.f;
            A[r] = pk(re_, im_);
        }

        float acc = 0.f;

        #pragma unroll 1      // keep code small (I$: R9 lesson)
        for (int l = 0; l < 3; l++) {
            // ======== Pass A: wires 0-3 pair (r bits), wires 12,13 shfl ========
            if (l) {
                // gray-folded CNOT perm of previous layer
                #pragma unroll
                for (int r = 0; r < 16; r++)
                    A[r] = psi[baseA_ld ^ (((r ^ (r << 1)) & 31) << 9)];
                __syncthreads();   // gather set != scatter set
            }
            #pragma unroll
            for (int w = 12; w < 14; w++) {
                const ull* g = (const ull*)(aux + OF_GATE + (l * 14 + w) * 8);
                int bit = 13 - w;
                ull ca2 = g[0];
                ull sp  = ((lane >> bit) & 1) ? g[2] : g[1];
                unsigned mask = 1u << bit;
                #pragma unroll
                for (int r = 0; r < 16; r++)
                    shfl_ry(A[r], mask, ca2, sp);
            }
            #pragma unroll
            for (int w = 0; w < 4; w++) {
                const ull* g = (const ull*)(aux + OF_GATE + (l * 14 + w) * 8);
                ull ca2 = g[0], nsa2 = g[1], sa2 = g[2];
                int bj = 1 << (3 - w);
                #pragma unroll
                for (int r = 0; r < 16; r++)
                    if (!(r & bj))
                        pair_ry(A[r], A[r | bj], ca2, nsa2, sa2);
            }
            #pragma unroll
            for (int r = 0; r < 16; r++)
                psi[baseA_st | (r << 10)] = A[r];
            __syncthreads();

            // ======== Pass B: wires 4-7 pair ========
            #pragma unroll
            for (int r = 0; r < 16; r++)
                A[r] = psi[base_B ^ ((r << 6) | ((r & 7) << 2))];
            #pragma unroll
            for (int w = 4; w < 8; w++) {
                const ull* g = (const ull*)(aux + OF_GATE + (l * 14 + w) * 8);
                ull ca2 = g[0], nsa2 = g[1], sa2 = g[2];
                int bj = 1 << (7 - w);
                #pragma unroll
                for (int r = 0; r < 16; r++)
                    if (!(r & bj))
                        pair_ry(A[r], A[r | bj], ca2, nsa2, sa2);
            }
            #pragma unroll
            for (int r = 0; r < 16; r++)
                psi[base_B ^ ((r << 6) | ((r & 7) << 2))] = A[r];
            __syncthreads();

            // ======== Pass C: wires 8-11 pair ========
            #pragma unroll
            for (int r = 0; r < 16; r++)
                A[r] = psi[base_C ^ (r << 2)];
            #pragma unroll
            for (int w = 8; w < 12; w++) {
                const ull* g = (const ull*)(aux + OF_GATE + (l * 14 + w) * 8);
                ull ca2 = g[0], nsa2 = g[1], sa2 = g[2];
                int bj = 1 << (11 - w);
                #pragma unroll
                for (int r = 0; r < 16; r++)
                    if (!(r & bj))
                        pair_ry(A[r], A[r | bj], ca2, nsa2, sa2);
            }

            if (l < 2) {
                // ---- all 14 wires' RZ phases once: TL[lane]*TH[wa]*PR[r] ----
                const float* tl = aux + OF_TL + (l * 32 + lane) * 2;
                const float* th = aux + OF_TH + (l * 32 + wa) * 2;
                float c1 = tl[0], s1 = tl[1], c2 = th[0], s2 = th[1];
                float C = c1 * c2 - s1 * s2;
                float S = s1 * c2 + c1 * s2;
                ull tpc = pk(C, C), tpn = pk(-S, S);
                const ull* pr = (const ull*)(aux + OF_PR + l * 64);
                #pragma unroll
                for (int r = 0; r < 16; r++) {
                    ull tv = phmul(A[r], tpc, tpn);
                    A[r] = phmul(tv, pr[2 * r], pr[2 * r + 1]);
                }
                #pragma unroll
                for (int r = 0; r < 16; r++)
                    psi[base_C ^ (r << 2)] = A[r];
                __syncthreads();
            } else {
                // last layer: phases unobservable; fold final perm + <Z> + head
                #pragma unroll
                for (int r = 0; r < 16; r++) {
                    int gg = ggB ^ dgray4(r);
                    float wt = aux[OF_TLO + (gg & 127)] + aux[OF_THI + ((gg >> 7) & 127)];
                    float x, y; upk(A[r], x, y);
                    acc = fmaf(fmaf(x, x, y * y), wt, acc);
                }
            }
        }

        // ---- block reduction ----
        #pragma unroll
        for (int o = 16; o; o >>= 1)
            acc += __shfl_xor_sync(0xffffffffu, acc, o);
        if (lane == 0)
            aux[OF_WARP + wa] = acc;
        __syncthreads();
        if (tid < 32) {
            float v = aux[OF_WARP + tid];
            #pragma unroll
            for (int o = 16; o; o >>= 1)
                v += __shfl_xor_sync(0xffffffffu, v, o);
            if (tid == 0)
                out[s] = v + hb[0];
        }
    }
}

extern "C" void kernel_launch(void* const* d_in, const int* in_sizes, int n_in,
                              void* d_out, int out_size)
{
    const float* state = (const float*)d_in[0];
    const float* vp    = (const float*)d_in[1];
    const float* hw    = (const float*)d_in[2];
    const float* hb    = (const float*)d_in[3];
    float* out = (float*)d_out;

    cudaFuncSetAttribute(qsim_kernel,
                         cudaFuncAttributeMaxDynamicSharedMemorySize,
                         (int)SMEM_BYTES);
    qsim_kernel<<<GRID, THREADS, SMEM_BYTES>>>(state, vp, hw, hb, out);
}